// round 1
// baseline (speedup 1.0000x reference)
#include <cuda_runtime.h>

// Problem constants (fixed by the dataset).
#define DIM     64
#define NMAX    262144
#define NLMAX   1024
#define TC      128   // centroids per shared-memory tile

__device__ int   g_assign[NMAX];
__device__ float g_csq[NLMAX];

typedef unsigned long long u64;

// Packed fp32x2 FMA / ADD (sm_100+ PTX; SASS FFMA2 — 2x fp32 rate vs FFMA-3reg).
__device__ __forceinline__ u64 ffma2(u64 a, u64 b, u64 c) {
    u64 d;
    asm("fma.rn.f32x2 %0, %1, %2, %3;" : "=l"(d) : "l"(a), "l"(b), "l"(c));
    return d;
}
__device__ __forceinline__ u64 fadd2(u64 a, u64 b) {
    u64 d;
    asm("add.rn.f32x2 %0, %1, %2;" : "=l"(d) : "l"(a), "l"(b));
    return d;
}
__device__ __forceinline__ float2 unpack2(u64 v) {
    float2 f;
    asm("mov.b64 {%0, %1}, %2;" : "=f"(f.x), "=f"(f.y) : "l"(v));
    return f;
}

// ---------------------------------------------------------------------------
// Kernel 0: per-centroid squared norms.
// ---------------------------------------------------------------------------
__global__ void csq_kernel(const float* __restrict__ cents, int nlist) {
    int c = blockIdx.x * blockDim.x + threadIdx.x;
    if (c < nlist) {
        const float4* row = reinterpret_cast<const float4*>(cents + (size_t)c * DIM);
        float s = 0.f;
        #pragma unroll
        for (int k = 0; k < DIM / 4; k++) {
            float4 r = row[k];
            s += r.x * r.x + r.y * r.y + r.z * r.z + r.w * r.w;
        }
        g_csq[c] = s;
    }
}

// ---------------------------------------------------------------------------
// Kernel 1: argmin assignment. One thread per vector; centroid tiles in smem.
// Compare c_sq - 2*dot (x_sq is constant per row -> same argmin as full d2).
// Strict '<' with ascending scan matches jnp.argmin first-occurrence ties.
// ---------------------------------------------------------------------------
__global__ __launch_bounds__(256, 2)
void assign_kernel(const float* __restrict__ vecs,
                   const float* __restrict__ cents,
                   int n, int nlist) {
    __shared__ float sc[TC * DIM];     // 32 KB tile
    __shared__ float scsq[TC];

    const int i = blockIdx.x * 256 + threadIdx.x;

    // Vector row in registers as 16x ulonglong2 (= 32 packed f32x2 operands).
    ulonglong2 vv[DIM / 4];
    if (i < n) {
        const ulonglong2* vrow =
            reinterpret_cast<const ulonglong2*>(vecs + (size_t)i * DIM);
        #pragma unroll
        for (int k = 0; k < DIM / 4; k++) vv[k] = vrow[k];
    }

    float best = 3.4e38f;
    int   bidx = 0;

    for (int t = 0; t < nlist; t += TC) {
        // Cooperative, coalesced tile load: 2048 float4 / 256 threads = 8 each.
        {
            const float4* src = reinterpret_cast<const float4*>(cents + (size_t)t * DIM);
            float4* dst = reinterpret_cast<float4*>(sc);
            #pragma unroll
            for (int k = 0; k < (TC * DIM / 4) / 256; k++)
                dst[threadIdx.x + k * 256] = src[threadIdx.x + k * 256];
            if (threadIdx.x < TC) scsq[threadIdx.x] = g_csq[t + threadIdx.x];
        }
        __syncthreads();

        if (i < n) {
            #pragma unroll 2
            for (int c = 0; c < TC; c++) {
                const ulonglong2* crow =
                    reinterpret_cast<const ulonglong2*>(sc + c * DIM);
                u64 a0 = 0ull, a1 = 0ull, a2 = 0ull, a3 = 0ull;
                #pragma unroll
                for (int k = 0; k < DIM / 4; k += 2) {
                    ulonglong2 c0 = crow[k];      // broadcast LDS.128, conflict-free
                    ulonglong2 c1 = crow[k + 1];
                    a0 = ffma2(vv[k].x,     c0.x, a0);
                    a1 = ffma2(vv[k].y,     c0.y, a1);
                    a2 = ffma2(vv[k + 1].x, c1.x, a2);
                    a3 = ffma2(vv[k + 1].y, c1.y, a3);
                }
                a0 = fadd2(a0, a1);
                a2 = fadd2(a2, a3);
                a0 = fadd2(a0, a2);
                float2 f = unpack2(a0);
                float dot = f.x + f.y;
                float d2  = fmaf(-2.f, dot, scsq[c]);
                if (d2 < best) { best = d2; bidx = t + c; }
            }
        }
        __syncthreads();
    }

    if (i < n) g_assign[i] = bidx;
}

// ---------------------------------------------------------------------------
// Kernel 2: coalesced gather of winning centroid rows. One thread per float4.
// Centroids (256 KB) are fully L2-resident -> read side is cheap.
// ---------------------------------------------------------------------------
__global__ void gather_kernel(const float* __restrict__ cents,
                              float* __restrict__ out, int n) {
    int gid = blockIdx.x * blockDim.x + threadIdx.x;
    if (gid < n * (DIM / 4)) {
        int v = gid >> 4;          // vector index
        int j = gid & 15;          // float4 within row
        reinterpret_cast<float4*>(out)[gid] =
            reinterpret_cast<const float4*>(cents)[g_assign[v] * (DIM / 4) + j];
    }
}

// ---------------------------------------------------------------------------
extern "C" void kernel_launch(void* const* d_in, const int* in_sizes, int n_in,
                              void* d_out, int out_size) {
    const float* vecs  = (const float*)d_in[0];
    const float* cents = (const float*)d_in[1];
    float*       out   = (float*)d_out;

    const int n     = in_sizes[0] / DIM;   // 262144
    const int nlist = in_sizes[1] / DIM;   // 1024

    csq_kernel<<<(nlist + 255) / 256, 256>>>(cents, nlist);
    assign_kernel<<<(n + 255) / 256, 256>>>(vecs, cents, n, nlist);

    const int nvec4 = n * (DIM / 4);
    gather_kernel<<<(nvec4 + 255) / 256, 256>>>(cents, out, n);
}

// round 3
// speedup vs baseline: 1.9680x; 1.9680x over previous
#include <cuda_runtime.h>

// Problem constants (fixed by the dataset).
#define DIM     64
#define NMAX    262144
#define NLMAX   1024

#define BM      128   // vectors per block tile
#define BN      64    // centroids per smem tile
#define TV      8     // vectors per thread
#define TCN     4     // centroids per thread
#define PAD     68    // padded smem row stride in floats (2-way conflict max)

__device__ int   g_assign[NMAX];
__device__ float g_csq[NLMAX];

typedef unsigned long long u64;

// Packed fp32x2 FMA (sm_100+; SASS FFMA2 — only reachable via PTX).
__device__ __forceinline__ u64 ffma2(u64 a, u64 b, u64 c) {
    u64 d;
    asm("fma.rn.f32x2 %0, %1, %2, %3;" : "=l"(d) : "l"(a), "l"(b), "l"(c));
    return d;
}
__device__ __forceinline__ float2 unpack2(u64 v) {
    float2 f;
    asm("mov.b64 {%0, %1}, %2;" : "=f"(f.x), "=f"(f.y) : "l"(v));
    return f;
}

// ---------------------------------------------------------------------------
// Kernel 0: per-centroid squared norms.
// ---------------------------------------------------------------------------
__global__ void csq_kernel(const float* __restrict__ cents, int nlist) {
    int c = blockIdx.x * blockDim.x + threadIdx.x;
    if (c < nlist) {
        const float4* row = reinterpret_cast<const float4*>(cents + (size_t)c * DIM);
        float s = 0.f;
        #pragma unroll
        for (int k = 0; k < DIM / 4; k++) {
            float4 r = row[k];
            s += r.x * r.x + r.y * r.y + r.z * r.z + r.w * r.w;
        }
        g_csq[c] = s;
    }
}

// ---------------------------------------------------------------------------
// Kernel 1: register-blocked assignment (SGEMM-style).
// Block: 256 threads as 16(tx: vec dim) x 16(ty: cent dim).
// Thread tile: 8 vecs (rows tx+16j) x 4 cents (rows ty+16c).
// Accumulator lanes = (even-k partial, odd-k partial) -> no operand dup for FFMA2.
// Compare c_sq - 2*dot (x_sq constant per row -> same argmin).
// ---------------------------------------------------------------------------
__global__ __launch_bounds__(256, 2)
void assign_kernel(const float* __restrict__ vecs,
                   const float* __restrict__ cents,
                   int n, int nlist) {
    extern __shared__ float sm[];
    float* svec  = sm;                        // [BM][PAD]
    float* scent = svec + BM * PAD;           // [BN][PAD]
    float* scsq  = scent + BN * PAD;          // [BN]
    float* sredd = scsq + BN;                 // [16][BM]
    int*   sredi = (int*)(sredd + 16 * BM);   // [16][BM]

    const int tid = threadIdx.x;
    const int tx  = tid & 15;
    const int ty  = tid >> 4;
    const int vbase = blockIdx.x * BM;

    // Load vec tile: 128 rows x 16 float4 = 2048 float4 / 256 threads = 8 each.
    #pragma unroll
    for (int k = 0; k < 8; k++) {
        int idx = tid + 256 * k;
        int r = idx >> 4, c4 = idx & 15;
        float4 val = reinterpret_cast<const float4*>(vecs)[(size_t)(vbase + r) * 16 + c4];
        *reinterpret_cast<float4*>(&svec[r * PAD + c4 * 4]) = val;
    }

    float bestd[TV];
    int   besti[TV];
    #pragma unroll
    for (int j = 0; j < TV; j++) { bestd[j] = 3.4e38f; besti[j] = 0; }

    for (int t = 0; t < nlist; t += BN) {
        __syncthreads();   // protect scent from previous iteration's readers
        // Load cent tile: 64 rows x 16 float4 = 1024 float4 / 256 threads = 4 each.
        #pragma unroll
        for (int k = 0; k < 4; k++) {
            int idx = tid + 256 * k;
            int r = idx >> 4, c4 = idx & 15;
            float4 val = reinterpret_cast<const float4*>(cents)[(size_t)(t + r) * 16 + c4];
            *reinterpret_cast<float4*>(&scent[r * PAD + c4 * 4]) = val;
        }
        if (tid < BN) scsq[tid] = g_csq[t + tid];
        __syncthreads();

        u64 acc[TV][TCN];
        #pragma unroll
        for (int j = 0; j < TV; j++)
            #pragma unroll
            for (int c = 0; c < TCN; c++) acc[j][c] = 0ull;

        #pragma unroll
        for (int k4 = 0; k4 < DIM / 4; k4++) {
            ulonglong2 vv[TV];
            ulonglong2 cc[TCN];
            #pragma unroll
            for (int j = 0; j < TV; j++)
                vv[j] = *reinterpret_cast<const ulonglong2*>(
                            &svec[(tx + 16 * j) * PAD + k4 * 4]);
            #pragma unroll
            for (int c = 0; c < TCN; c++)
                cc[c] = *reinterpret_cast<const ulonglong2*>(
                            &scent[(ty + 16 * c) * PAD + k4 * 4]);
            #pragma unroll
            for (int j = 0; j < TV; j++)
                #pragma unroll
                for (int c = 0; c < TCN; c++) {
                    acc[j][c] = ffma2(vv[j].x, cc[c].x, acc[j][c]);
                    acc[j][c] = ffma2(vv[j].y, cc[c].y, acc[j][c]);
                }
        }

        // Per-tile epilogue: fold lanes, form d2, update running best.
        // c ascending => centroid indices ascending within thread (ties: first wins).
        #pragma unroll
        for (int c = 0; c < TCN; c++) {
            int   ci = t + ty + 16 * c;
            float cs = scsq[ty + 16 * c];
            #pragma unroll
            for (int j = 0; j < TV; j++) {
                float2 f  = unpack2(acc[j][c]);
                float  d2 = fmaf(-2.f, f.x + f.y, cs);
                if (d2 < bestd[j]) { bestd[j] = d2; besti[j] = ci; }
            }
        }
    }

    // Cross-thread reduction: 16 ty-candidates per vector.
    #pragma unroll
    for (int j = 0; j < TV; j++) {
        int v = tx + 16 * j;
        sredd[ty * BM + v] = bestd[j];
        sredi[ty * BM + v] = besti[j];
    }
    __syncthreads();
    if (tid < BM) {
        float bd = sredd[tid];
        int   bi = sredi[tid];
        #pragma unroll
        for (int r = 1; r < 16; r++) {
            float d  = sredd[r * BM + tid];
            int   i2 = sredi[r * BM + tid];
            if (d < bd || (d == bd && i2 < bi)) { bd = d; bi = i2; }
        }
        g_assign[vbase + tid] = bi;
    }
}

// ---------------------------------------------------------------------------
// Kernel 2: coalesced gather of winning centroid rows (cents L2-resident).
// ---------------------------------------------------------------------------
__global__ void gather_kernel(const float* __restrict__ cents,
                              float* __restrict__ out, int n) {
    int gid = blockIdx.x * blockDim.x + threadIdx.x;
    if (gid < n * (DIM / 4)) {
        int v = gid >> 4;
        int j = gid & 15;
        reinterpret_cast<float4*>(out)[gid] =
            reinterpret_cast<const float4*>(cents)[g_assign[v] * (DIM / 4) + j];
    }
}

// ---------------------------------------------------------------------------
extern "C" void kernel_launch(void* const* d_in, const int* in_sizes, int n_in,
                              void* d_out, int out_size) {
    const float* vecs  = (const float*)d_in[0];
    const float* cents = (const float*)d_in[1];
    float*       out   = (float*)d_out;

    const int n     = in_sizes[0] / DIM;   // 262144
    const int nlist = in_sizes[1] / DIM;   // 1024

    const int smem_bytes = (BM * PAD + BN * PAD + BN + 16 * BM) * 4  // floats
                         + 16 * BM * 4;                              // int indices
    cudaFuncSetAttribute(assign_kernel,
                         cudaFuncAttributeMaxDynamicSharedMemorySize, smem_bytes);

    csq_kernel<<<(nlist + 255) / 256, 256>>>(cents, nlist);
    assign_kernel<<<n / BM, 256, smem_bytes>>>(vecs, cents, n, nlist);

    const int nvec4 = n * (DIM / 4);
    gather_kernel<<<(nvec4 + 255) / 256, 256>>>(cents, out, n);
}

// round 6
// speedup vs baseline: 4.4779x; 2.2754x over previous
#include <cuda_runtime.h>
#include <cstdint>

#define DIM     64
#define NMAX    262144
#define NLMAX   1024
#define TAU     0.3f
#define SPAD    68

__device__ int   g_assign[NMAX];
__device__ float g_csq[NLMAX];
__device__ int   g_nrescue;
__device__ int   g_rescue[NMAX];

typedef unsigned long long u64;

// Packed fp32x2 FMA (sm_100+ FFMA2) for the exact rescue pass.
__device__ __forceinline__ u64 ffma2(u64 a, u64 b, u64 c) {
    u64 d;
    asm("fma.rn.f32x2 %0, %1, %2, %3;" : "=l"(d) : "l"(a), "l"(b), "l"(c));
    return d;
}
__device__ __forceinline__ float2 unpack2(u64 v) {
    float2 f;
    asm("mov.b64 {%0, %1}, %2;" : "=f"(f.x), "=f"(f.y) : "l"(v));
    return f;
}

// tf32 tensor-core MMA (Ampere-class PTX; compiles for compute_103).
__device__ __forceinline__ void mma_tf32(float c[4], const uint32_t a[4],
                                         const uint32_t b[2]) {
    asm volatile(
        "mma.sync.aligned.m16n8k8.row.col.f32.tf32.tf32.f32 "
        "{%0,%1,%2,%3}, {%4,%5,%6,%7}, {%8,%9}, {%0,%1,%2,%3};"
        : "+f"(c[0]), "+f"(c[1]), "+f"(c[2]), "+f"(c[3])
        : "r"(a[0]), "r"(a[1]), "r"(a[2]), "r"(a[3]), "r"(b[0]), "r"(b[1]));
}

// ---------------------------------------------------------------------------
// Kernel 0: centroid squared norms + rescue-counter reset.
// ---------------------------------------------------------------------------
__global__ void csq_kernel(const float* __restrict__ cents, int nlist) {
    if (blockIdx.x == 0 && threadIdx.x == 0) g_nrescue = 0;
    int c = blockIdx.x * blockDim.x + threadIdx.x;
    if (c < nlist) {
        const float4* row = reinterpret_cast<const float4*>(cents + (size_t)c * DIM);
        float s = 0.f;
        #pragma unroll
        for (int k = 0; k < DIM / 4; k++) {
            float4 r = row[k];
            s += r.x * r.x + r.y * r.y + r.z * r.z + r.w * r.w;
        }
        g_csq[c] = s;
    }
}

// ---------------------------------------------------------------------------
// Kernel 1: tf32 mma.sync assignment.
// CTA tile M=128, loop 8 tiles of 128 cents, K=64.
// 8 warps as 4(M) x 2(N): warp tile 32x64 -> 2x8 m16n8k8 fragments.
// d2_approx = csq - 2*dot (x_sq constant per row). Track (min1, min2, argmin);
// rows with min2-min1 < TAU go to the exact-fp32 rescue kernel.
// ---------------------------------------------------------------------------
#define SB_F    (128 * SPAD)            // 8704 floats
#define SCSQ_F  (2 * 128 * SPAD)        // 17408
#define SRED_F  (SCSQ_F + NLMAX)        // 18432
#define SMEM_F  (SRED_F + 3 * 256)      // + d1/d2 [2][128] + idx [2][128]
#define SMEM_B  (SMEM_F * 4)            // 76800 bytes

__global__ __launch_bounds__(256, 2)
void assign_mma_kernel(const float* __restrict__ vecs,
                       const float* __restrict__ cents) {
    extern __shared__ float sm[];
    float* sA    = sm;
    float* sB    = sm + SB_F;
    float* scsq  = sm + SCSQ_F;
    float* sred1 = sm + SRED_F;              // [2][128] min1
    float* sred2 = sred1 + 256;              // [2][128] min2
    int*   sredi = (int*)(sred2 + 256);      // [2][128] argmin

    const int tid  = threadIdx.x;
    const int lane = tid & 31;
    const int wid  = tid >> 5;
    const int g    = lane >> 2;              // fragment groupID (row)
    const int tig  = lane & 3;               // thread-in-group (col/k)
    const int moff = (wid >> 1) * 32;
    const int noff = (wid & 1) * 64;
    const int vbase = blockIdx.x * 128;

    // A tile: 128 rows x 16 float4, padded rows (conflict-free frag loads).
    #pragma unroll
    for (int k = 0; k < 8; k++) {
        int idx = tid + 256 * k;
        int r = idx >> 4, c4 = idx & 15;
        float4 v = reinterpret_cast<const float4*>(vecs)[(size_t)(vbase + r) * 16 + c4];
        *reinterpret_cast<float4*>(&sA[r * SPAD + c4 * 4]) = v;
    }
    #pragma unroll
    for (int k = 0; k < 4; k++) scsq[tid + 256 * k] = g_csq[tid + 256 * k];

    // Per-thread state for 4 rows: s = mt*2 + hi -> row moff + mt*16 + hi*8 + g.
    float m1[4], m2[4];
    int   bi[4];
    #pragma unroll
    for (int s = 0; s < 4; s++) { m1[s] = 3.4e38f; m2[s] = 3.4e38f; bi[s] = 0; }

    for (int t = 0; t < 8; t++) {
        // Prefetch B tile to regs (overlaps previous tile's MMA+epilogue).
        float4 pf[8];
        int rr[8], cc[8];
        #pragma unroll
        for (int k = 0; k < 8; k++) {
            int idx = tid + 256 * k;
            rr[k] = idx >> 4; cc[k] = idx & 15;
            pf[k] = reinterpret_cast<const float4*>(cents)
                        [(size_t)(t * 128 + rr[k]) * 16 + cc[k]];
        }
        __syncthreads();                     // everyone done reading sB
        #pragma unroll
        for (int k = 0; k < 8; k++)
            *reinterpret_cast<float4*>(&sB[rr[k] * SPAD + cc[k] * 4]) = pf[k];
        __syncthreads();

        float c[2][8][4];
        #pragma unroll
        for (int mt = 0; mt < 2; mt++)
            #pragma unroll
            for (int nf = 0; nf < 8; nf++)
                #pragma unroll
                for (int q = 0; q < 4; q++) c[mt][nf][q] = 0.f;

        #pragma unroll
        for (int k8 = 0; k8 < 8; k8++) {
            const int k0 = k8 * 8;
            uint32_t a[2][4], b[8][2];
            #pragma unroll
            for (int mt = 0; mt < 2; mt++) {
                const float* base = &sA[(moff + mt * 16 + g) * SPAD + k0 + tig];
                a[mt][0] = __float_as_uint(base[0]);
                a[mt][1] = __float_as_uint(base[8 * SPAD]);
                a[mt][2] = __float_as_uint(base[4]);
                a[mt][3] = __float_as_uint(base[8 * SPAD + 4]);
            }
            #pragma unroll
            for (int nf = 0; nf < 8; nf++) {
                const float* base = &sB[(noff + nf * 8 + g) * SPAD + k0 + tig];
                b[nf][0] = __float_as_uint(base[0]);
                b[nf][1] = __float_as_uint(base[4]);
            }
            #pragma unroll
            for (int mt = 0; mt < 2; mt++)
                #pragma unroll
                for (int nf = 0; nf < 8; nf++)
                    mma_tf32(c[mt][nf], a[mt], b[nf]);
        }

        // Epilogue: fold csq, update running top-2 minima.
        #pragma unroll
        for (int nf = 0; nf < 8; nf++) {
            int   cb  = t * 128 + noff + nf * 8 + 2 * tig;
            float cs0 = scsq[cb], cs1 = scsq[cb + 1];
            #pragma unroll
            for (int mt = 0; mt < 2; mt++) {
                const int s0 = mt * 2, s1 = mt * 2 + 1;
                float d;
                d = fmaf(-2.f, c[mt][nf][0], cs0);
                if (d < m1[s0]) { m2[s0] = m1[s0]; m1[s0] = d; bi[s0] = cb; }
                else            { m2[s0] = fminf(m2[s0], d); }
                d = fmaf(-2.f, c[mt][nf][1], cs1);
                if (d < m1[s0]) { m2[s0] = m1[s0]; m1[s0] = d; bi[s0] = cb + 1; }
                else            { m2[s0] = fminf(m2[s0], d); }
                d = fmaf(-2.f, c[mt][nf][2], cs0);
                if (d < m1[s1]) { m2[s1] = m1[s1]; m1[s1] = d; bi[s1] = cb; }
                else            { m2[s1] = fminf(m2[s1], d); }
                d = fmaf(-2.f, c[mt][nf][3], cs1);
                if (d < m1[s1]) { m2[s1] = m1[s1]; m1[s1] = d; bi[s1] = cb + 1; }
                else            { m2[s1] = fminf(m2[s1], d); }
            }
        }
    }

    // Quad reduction (lanes sharing g hold the same 4 rows; tig differs).
    #pragma unroll
    for (int off = 1; off <= 2; off <<= 1) {
        #pragma unroll
        for (int s = 0; s < 4; s++) {
            float om1 = __shfl_xor_sync(0xffffffffu, m1[s], off);
            float om2 = __shfl_xor_sync(0xffffffffu, m2[s], off);
            int   oi  = __shfl_xor_sync(0xffffffffu, bi[s], off);
            bool better = (om1 < m1[s]) || (om1 == m1[s] && oi < bi[s]);
            m2[s] = fminf(fminf(m2[s], om2), fmaxf(m1[s], om1));
            m1[s] = fminf(m1[s], om1);
            if (better) bi[s] = oi;
        }
    }
    const int half = wid & 1;
    if (tig == 0) {
        #pragma unroll
        for (int s = 0; s < 4; s++) {
            int row = moff + (s >> 1) * 16 + (s & 1) * 8 + g;
            sred1[half * 128 + row] = m1[s];
            sred2[half * 128 + row] = m2[s];
            sredi[half * 128 + row] = bi[s];
        }
    }
    __syncthreads();
    if (tid < 128) {
        float a1 = sred1[tid],   b1 = sred1[128 + tid];
        float a2 = sred2[tid],   b2 = sred2[128 + tid];
        int   ai = sredi[tid],   bx = sredi[128 + tid];
        bool  bb = (b1 < a1) || (b1 == a1 && bx < ai);
        float g1 = fminf(a1, b1);
        float g2 = fminf(fminf(a2, b2), fmaxf(a1, b1));
        g_assign[vbase + tid] = bb ? bx : ai;
        if (g2 - g1 < TAU) {
            int p = atomicAdd(&g_nrescue, 1);
            g_rescue[p] = vbase + tid;
        }
    }
}

// ---------------------------------------------------------------------------
// Kernel 2: exact-fp32 rescue for ambiguous rows (register-blocked, FFMA2).
// ---------------------------------------------------------------------------
#define BM   128
#define BN   64
#define TV   8
#define TCN  4
#define PAD  68

__global__ __launch_bounds__(256, 2)
void rescue_kernel(const float* __restrict__ vecs,
                   const float* __restrict__ cents, int nlist) {
    const int cnt = g_nrescue;
    if (blockIdx.x * BM >= cnt) return;

    extern __shared__ float sm[];
    float* svec  = sm;                        // [BM][PAD]
    float* scent = svec + BM * PAD;           // [BN][PAD]
    float* scsq  = scent + BN * PAD;          // [BN]
    float* sredd = scsq + BN;                 // [16][BM]
    int*   sredi = (int*)(sredd + 16 * BM);   // [16][BM]
    int*   srow  = sredi + 16 * BM;           // [BM]

    const int tid = threadIdx.x;
    const int tx  = tid & 15;
    const int ty  = tid >> 4;
    const int base = blockIdx.x * BM;

    if (tid < BM) {
        int p = base + tid;
        srow[tid] = g_rescue[p < cnt ? p : cnt - 1];
    }
    __syncthreads();

    #pragma unroll
    for (int k = 0; k < 8; k++) {
        int idx = tid + 256 * k;
        int r = idx >> 4, c4 = idx & 15;
        float4 val = reinterpret_cast<const float4*>(vecs)[(size_t)srow[r] * 16 + c4];
        *reinterpret_cast<float4*>(&svec[r * PAD + c4 * 4]) = val;
    }

    float bestd[TV];
    int   besti[TV];
    #pragma unroll
    for (int j = 0; j < TV; j++) { bestd[j] = 3.4e38f; besti[j] = 0; }

    for (int t = 0; t < nlist; t += BN) {
        __syncthreads();
        #pragma unroll
        for (int k = 0; k < 4; k++) {
            int idx = tid + 256 * k;
            int r = idx >> 4, c4 = idx & 15;
            float4 val = reinterpret_cast<const float4*>(cents)[(size_t)(t + r) * 16 + c4];
            *reinterpret_cast<float4*>(&scent[r * PAD + c4 * 4]) = val;
        }
        if (tid < BN) scsq[tid] = g_csq[t + tid];
        __syncthreads();

        u64 acc[TV][TCN];
        #pragma unroll
        for (int j = 0; j < TV; j++)
            #pragma unroll
            for (int c = 0; c < TCN; c++) acc[j][c] = 0ull;

        #pragma unroll
        for (int k4 = 0; k4 < DIM / 4; k4++) {
            ulonglong2 vv[TV], cc[TCN];
            #pragma unroll
            for (int j = 0; j < TV; j++)
                vv[j] = *reinterpret_cast<const ulonglong2*>(
                            &svec[(tx + 16 * j) * PAD + k4 * 4]);
            #pragma unroll
            for (int c = 0; c < TCN; c++)
                cc[c] = *reinterpret_cast<const ulonglong2*>(
                            &scent[(ty + 16 * c) * PAD + k4 * 4]);
            #pragma unroll
            for (int j = 0; j < TV; j++)
                #pragma unroll
                for (int c = 0; c < TCN; c++) {
                    acc[j][c] = ffma2(vv[j].x, cc[c].x, acc[j][c]);
                    acc[j][c] = ffma2(vv[j].y, cc[c].y, acc[j][c]);
                }
        }

        #pragma unroll
        for (int c = 0; c < TCN; c++) {
            int   ci = t + ty + 16 * c;
            float cs = scsq[ty + 16 * c];
            #pragma unroll
            for (int j = 0; j < TV; j++) {
                float2 f  = unpack2(acc[j][c]);
                float  d2 = fmaf(-2.f, f.x + f.y, cs);
                if (d2 < bestd[j]) { bestd[j] = d2; besti[j] = ci; }
            }
        }
    }

    #pragma unroll
    for (int j = 0; j < TV; j++) {
        int v = tx + 16 * j;
        sredd[ty * BM + v] = bestd[j];
        sredi[ty * BM + v] = besti[j];
    }
    __syncthreads();
    if (tid < BM) {
        float bd = sredd[tid];
        int   bi2 = sredi[tid];
        #pragma unroll
        for (int r = 1; r < 16; r++) {
            float d  = sredd[r * BM + tid];
            int   i2 = sredi[r * BM + tid];
            if (d < bd || (d == bd && i2 < bi2)) { bd = d; bi2 = i2; }
        }
        g_assign[srow[tid]] = bi2;
    }
}

// ---------------------------------------------------------------------------
// Kernel 3: coalesced gather of winning centroid rows (cents L2-resident).
// ---------------------------------------------------------------------------
__global__ void gather_kernel(const float* __restrict__ cents,
                              float* __restrict__ out, int n) {
    int gid = blockIdx.x * blockDim.x + threadIdx.x;
    if (gid < n * (DIM / 4)) {
        int v = gid >> 4, j = gid & 15;
        reinterpret_cast<float4*>(out)[gid] =
            reinterpret_cast<const float4*>(cents)[g_assign[v] * (DIM / 4) + j];
    }
}

// ---------------------------------------------------------------------------
extern "C" void kernel_launch(void* const* d_in, const int* in_sizes, int n_in,
                              void* d_out, int out_size) {
    const float* vecs  = (const float*)d_in[0];
    const float* cents = (const float*)d_in[1];
    float*       out   = (float*)d_out;

    const int n     = in_sizes[0] / DIM;   // 262144
    const int nlist = in_sizes[1] / DIM;   // 1024

    const int rescue_smem = (BM * PAD + BN * PAD + BN + 16 * BM) * 4
                          + 16 * BM * 4 + BM * 4;
    cudaFuncSetAttribute(assign_mma_kernel,
                         cudaFuncAttributeMaxDynamicSharedMemorySize, SMEM_B);
    cudaFuncSetAttribute(rescue_kernel,
                         cudaFuncAttributeMaxDynamicSharedMemorySize, rescue_smem);

    csq_kernel<<<(nlist + 255) / 256, 256>>>(cents, nlist);
    assign_mma_kernel<<<n / 128, 256, SMEM_B>>>(vecs, cents);
    rescue_kernel<<<n / BM, 256, rescue_smem>>>(vecs, cents, nlist);

    const int nvec4 = n * (DIM / 4);
    gather_kernel<<<(nvec4 + 255) / 256, 256>>>(cents, out, n);
}

// round 7
// speedup vs baseline: 4.5037x; 1.0058x over previous
#include <cuda_runtime.h>
#include <cstdint>

#define DIM     64
#define NMAX    262144
#define NLMAX   1024
#define TAU     0.3f
#define SPAD    68

__device__ float g_csq[NLMAX];
__device__ int   g_nrescue;
__device__ int   g_rescue[NMAX];

typedef unsigned long long u64;

// Packed fp32x2 FMA (sm_100+ FFMA2) for the exact rescue pass.
__device__ __forceinline__ u64 ffma2(u64 a, u64 b, u64 c) {
    u64 d;
    asm("fma.rn.f32x2 %0, %1, %2, %3;" : "=l"(d) : "l"(a), "l"(b), "l"(c));
    return d;
}
__device__ __forceinline__ float2 unpack2(u64 v) {
    float2 f;
    asm("mov.b64 {%0, %1}, %2;" : "=f"(f.x), "=f"(f.y) : "l"(v));
    return f;
}

// tf32 tensor-core MMA (Ampere-class PTX; compiles for compute_103).
__device__ __forceinline__ void mma_tf32(float c[4], const uint32_t a[4],
                                         const uint32_t b[2]) {
    asm volatile(
        "mma.sync.aligned.m16n8k8.row.col.f32.tf32.tf32.f32 "
        "{%0,%1,%2,%3}, {%4,%5,%6,%7}, {%8,%9}, {%0,%1,%2,%3};"
        : "+f"(c[0]), "+f"(c[1]), "+f"(c[2]), "+f"(c[3])
        : "r"(a[0]), "r"(a[1]), "r"(a[2]), "r"(a[3]), "r"(b[0]), "r"(b[1]));
}

__device__ __forceinline__ void cp16(uint32_t dst_smem, const void* src) {
    asm volatile("cp.async.cg.shared.global [%0], [%1], 16;"
                 :: "r"(dst_smem), "l"(src));
}
#define CP_COMMIT() asm volatile("cp.async.commit_group;" ::: "memory")
#define CP_WAIT(N)  asm volatile("cp.async.wait_group %0;" :: "n"(N) : "memory")

// ---------------------------------------------------------------------------
// Kernel 0: centroid squared norms + rescue-counter reset.
// ---------------------------------------------------------------------------
__global__ void csq_kernel(const float* __restrict__ cents, int nlist) {
    if (blockIdx.x == 0 && threadIdx.x == 0) g_nrescue = 0;
    int c = blockIdx.x * blockDim.x + threadIdx.x;
    if (c < nlist) {
        const float4* row = reinterpret_cast<const float4*>(cents + (size_t)c * DIM);
        float s = 0.f;
        #pragma unroll
        for (int k = 0; k < DIM / 4; k++) {
            float4 r = row[k];
            s += r.x * r.x + r.y * r.y + r.z * r.z + r.w * r.w;
        }
        g_csq[c] = s;
    }
}

// ---------------------------------------------------------------------------
// Kernel 1: tf32 mma.sync assignment + fused gather.
// CTA tile M=128, loop 8 tiles of 128 cents (cp.async double-buffered), K=64.
// 8 warps as 4(M) x 2(N): warp tile 32x64 -> 2x8 m16n8k8 fragments.
// d2_approx = csq - 2*dot. Track (min1, min2, argmin); rows with
// min2-min1 < TAU go to the exact-fp32 rescue kernel. Winning centroid rows
// are written straight to `out` (coalesced, all 256 threads).
// ---------------------------------------------------------------------------
#define SA_F    0
#define SB_F    (128 * SPAD)            // 8704 floats per buffer
#define SCSQ_F  (3 * 128 * SPAD)        // after A + 2 B buffers = 26112
#define SRED_F  (SCSQ_F + NLMAX)        // 27136
#define SBI_F   (SRED_F + 3 * 256)      // 27904
#define SMEM_F  (SBI_F + 128)           // 28032 floats
#define SMEM_B  (SMEM_F * 4)            // 112128 bytes

__global__ __launch_bounds__(256, 2)
void assign_mma_kernel(const float* __restrict__ vecs,
                       const float* __restrict__ cents,
                       float* __restrict__ out) {
    extern __shared__ float sm[];
    float* sA    = sm;
    float* scsq  = sm + SCSQ_F;
    float* sred1 = sm + SRED_F;              // [2][128] min1
    float* sred2 = sred1 + 256;              // [2][128] min2
    int*   sredi = (int*)(sred2 + 256);      // [2][128] argmin
    int*   sbi   = (int*)(sm + SBI_F);       // [128] final winner

    const int tid  = threadIdx.x;
    const int lane = tid & 31;
    const int wid  = tid >> 5;
    const int g    = lane >> 2;              // fragment groupID (row)
    const int tig  = lane & 3;               // thread-in-group (col/k)
    const int moff = (wid >> 1) * 32;
    const int noff = (wid & 1) * 64;
    const int vbase = blockIdx.x * 128;

    // Per-thread cp.async targets (same for every tile, both buffers).
    const int r_cp  = tid >> 4;              // row handled (x8 via +16 strides? no: idx scheme below)
    uint32_t sb_u32 = (uint32_t)__cvta_generic_to_shared(sm + SB_F);

    // Issue B tile 0 into buffer 0.
    #pragma unroll
    for (int k = 0; k < 8; k++) {
        int idx = tid + 256 * k;
        int r = idx >> 4, c4 = idx & 15;
        cp16(sb_u32 + (uint32_t)(r * SPAD + c4 * 4) * 4,
             cents + (size_t)r * DIM + c4 * 4);
    }
    CP_COMMIT();

    // A tile: 128 rows x 16 float4, padded rows (conflict-free frag loads).
    #pragma unroll
    for (int k = 0; k < 8; k++) {
        int idx = tid + 256 * k;
        int r = idx >> 4, c4 = idx & 15;
        float4 v = reinterpret_cast<const float4*>(vecs)[(size_t)(vbase + r) * 16 + c4];
        *reinterpret_cast<float4*>(&sA[r * SPAD + c4 * 4]) = v;
    }
    #pragma unroll
    for (int k = 0; k < 4; k++) scsq[tid + 256 * k] = g_csq[tid + 256 * k];

    // Per-thread state for 4 rows: s = mt*2 + hi -> row moff + mt*16 + hi*8 + g.
    float m1[4], m2[4];
    int   bi[4];
    #pragma unroll
    for (int s = 0; s < 4; s++) { m1[s] = 3.4e38f; m2[s] = 3.4e38f; bi[s] = 0; }

    for (int t = 0; t < 8; t++) {
        // Issue next tile into the other buffer (overlaps this tile's MMA).
        if (t < 7) {
            uint32_t dstb = sb_u32 + (uint32_t)(((t + 1) & 1) * SB_F) * 4;
            const float* srcb = cents + (size_t)(t + 1) * 128 * DIM;
            #pragma unroll
            for (int k = 0; k < 8; k++) {
                int idx = tid + 256 * k;
                int r = idx >> 4, c4 = idx & 15;
                cp16(dstb + (uint32_t)(r * SPAD + c4 * 4) * 4,
                     srcb + (size_t)r * DIM + c4 * 4);
            }
            CP_COMMIT();
            CP_WAIT(1);       // tile t complete (t+1 still in flight)
        } else {
            CP_WAIT(0);
        }
        __syncthreads();      // tile t visible to all warps

        const float* sB = sm + SB_F + (t & 1) * SB_F;

        float c[2][8][4];
        #pragma unroll
        for (int mt = 0; mt < 2; mt++)
            #pragma unroll
            for (int nf = 0; nf < 8; nf++)
                #pragma unroll
                for (int q = 0; q < 4; q++) c[mt][nf][q] = 0.f;

        #pragma unroll
        for (int k8 = 0; k8 < 8; k8++) {
            const int k0 = k8 * 8;
            uint32_t a[2][4], b[8][2];
            #pragma unroll
            for (int mt = 0; mt < 2; mt++) {
                const float* base = &sA[(moff + mt * 16 + g) * SPAD + k0 + tig];
                a[mt][0] = __float_as_uint(base[0]);
                a[mt][1] = __float_as_uint(base[8 * SPAD]);
                a[mt][2] = __float_as_uint(base[4]);
                a[mt][3] = __float_as_uint(base[8 * SPAD + 4]);
            }
            #pragma unroll
            for (int nf = 0; nf < 8; nf++) {
                const float* base = &sB[(noff + nf * 8 + g) * SPAD + k0 + tig];
                b[nf][0] = __float_as_uint(base[0]);
                b[nf][1] = __float_as_uint(base[4]);
            }
            #pragma unroll
            for (int mt = 0; mt < 2; mt++)
                #pragma unroll
                for (int nf = 0; nf < 8; nf++)
                    mma_tf32(c[mt][nf], a[mt], b[nf]);
        }

        // Epilogue: fold csq, update running top-2 minima.
        #pragma unroll
        for (int nf = 0; nf < 8; nf++) {
            int   cb  = t * 128 + noff + nf * 8 + 2 * tig;
            float cs0 = scsq[cb], cs1 = scsq[cb + 1];
            #pragma unroll
            for (int mt = 0; mt < 2; mt++) {
                const int s0 = mt * 2, s1 = mt * 2 + 1;
                float d;
                d = fmaf(-2.f, c[mt][nf][0], cs0);
                if (d < m1[s0]) { m2[s0] = m1[s0]; m1[s0] = d; bi[s0] = cb; }
                else            { m2[s0] = fminf(m2[s0], d); }
                d = fmaf(-2.f, c[mt][nf][1], cs1);
                if (d < m1[s0]) { m2[s0] = m1[s0]; m1[s0] = d; bi[s0] = cb + 1; }
                else            { m2[s0] = fminf(m2[s0], d); }
                d = fmaf(-2.f, c[mt][nf][2], cs0);
                if (d < m1[s1]) { m2[s1] = m1[s1]; m1[s1] = d; bi[s1] = cb; }
                else            { m2[s1] = fminf(m2[s1], d); }
                d = fmaf(-2.f, c[mt][nf][3], cs1);
                if (d < m1[s1]) { m2[s1] = m1[s1]; m1[s1] = d; bi[s1] = cb + 1; }
                else            { m2[s1] = fminf(m2[s1], d); }
            }
        }
        __syncthreads();      // MMA reads of buf[(t+1)&1] done before overwrite
    }

    // Quad reduction (lanes sharing g hold the same 4 rows; tig differs).
    #pragma unroll
    for (int off = 1; off <= 2; off <<= 1) {
        #pragma unroll
        for (int s = 0; s < 4; s++) {
            float om1 = __shfl_xor_sync(0xffffffffu, m1[s], off);
            float om2 = __shfl_xor_sync(0xffffffffu, m2[s], off);
            int   oi  = __shfl_xor_sync(0xffffffffu, bi[s], off);
            bool better = (om1 < m1[s]) || (om1 == m1[s] && oi < bi[s]);
            m2[s] = fminf(fminf(m2[s], om2), fmaxf(m1[s], om1));
            m1[s] = fminf(m1[s], om1);
            if (better) bi[s] = oi;
        }
    }
    const int half = wid & 1;
    if (tig == 0) {
        #pragma unroll
        for (int s = 0; s < 4; s++) {
            int row = moff + (s >> 1) * 16 + (s & 1) * 8 + g;
            sred1[half * 128 + row] = m1[s];
            sred2[half * 128 + row] = m2[s];
            sredi[half * 128 + row] = bi[s];
        }
    }
    __syncthreads();
    if (tid < 128) {
        float a1 = sred1[tid],   b1 = sred1[128 + tid];
        float a2 = sred2[tid],   b2 = sred2[128 + tid];
        int   ai = sredi[tid],   bx = sredi[128 + tid];
        bool  bb = (b1 < a1) || (b1 == a1 && bx < ai);
        float g1 = fminf(a1, b1);
        float g2 = fminf(fminf(a2, b2), fmaxf(a1, b1));
        sbi[tid] = bb ? bx : ai;
        if (g2 - g1 < TAU) {
            int p = atomicAdd(&g_nrescue, 1);
            g_rescue[p] = vbase + tid;
        }
    }
    __syncthreads();

    // Fused gather: coalesced write of winning centroid rows.
    #pragma unroll
    for (int k = 0; k < 8; k++) {
        int idx = tid + 256 * k;
        int r = idx >> 4, c4 = idx & 15;
        reinterpret_cast<float4*>(out)[(size_t)vbase * 16 + idx] =
            reinterpret_cast<const float4*>(cents)[sbi[r] * 16 + c4];
    }
}

// ---------------------------------------------------------------------------
// Kernel 2: exact-fp32 rescue for ambiguous rows (register-blocked, FFMA2).
// Overwrites the output rows it re-resolves.
// ---------------------------------------------------------------------------
#define BM   128
#define BN   64
#define TV   8
#define TCN  4
#define PAD  68

__global__ __launch_bounds__(256, 2)
void rescue_kernel(const float* __restrict__ vecs,
                   const float* __restrict__ cents,
                   float* __restrict__ out, int nlist) {
    const int cnt = g_nrescue;
    if (blockIdx.x * BM >= cnt) return;

    extern __shared__ float sm[];
    float* svec  = sm;                        // [BM][PAD]
    float* scent = svec + BM * PAD;           // [BN][PAD]
    float* scsq  = scent + BN * PAD;          // [BN]
    float* sredd = scsq + BN;                 // [16][BM]
    int*   sredi = (int*)(sredd + 16 * BM);   // [16][BM]
    int*   srow  = sredi + 16 * BM;           // [BM]

    const int tid = threadIdx.x;
    const int tx  = tid & 15;
    const int ty  = tid >> 4;
    const int base = blockIdx.x * BM;

    if (tid < BM) {
        int p = base + tid;
        srow[tid] = g_rescue[p < cnt ? p : cnt - 1];
    }
    __syncthreads();

    #pragma unroll
    for (int k = 0; k < 8; k++) {
        int idx = tid + 256 * k;
        int r = idx >> 4, c4 = idx & 15;
        float4 val = reinterpret_cast<const float4*>(vecs)[(size_t)srow[r] * 16 + c4];
        *reinterpret_cast<float4*>(&svec[r * PAD + c4 * 4]) = val;
    }

    float bestd[TV];
    int   besti[TV];
    #pragma unroll
    for (int j = 0; j < TV; j++) { bestd[j] = 3.4e38f; besti[j] = 0; }

    for (int t = 0; t < nlist; t += BN) {
        __syncthreads();
        #pragma unroll
        for (int k = 0; k < 4; k++) {
            int idx = tid + 256 * k;
            int r = idx >> 4, c4 = idx & 15;
            float4 val = reinterpret_cast<const float4*>(cents)[(size_t)(t + r) * 16 + c4];
            *reinterpret_cast<float4*>(&scent[r * PAD + c4 * 4]) = val;
        }
        if (tid < BN) scsq[tid] = g_csq[t + tid];
        __syncthreads();

        u64 acc[TV][TCN];
        #pragma unroll
        for (int j = 0; j < TV; j++)
            #pragma unroll
            for (int c = 0; c < TCN; c++) acc[j][c] = 0ull;

        #pragma unroll
        for (int k4 = 0; k4 < DIM / 4; k4++) {
            ulonglong2 vv[TV], cc[TCN];
            #pragma unroll
            for (int j = 0; j < TV; j++)
                vv[j] = *reinterpret_cast<const ulonglong2*>(
                            &svec[(tx + 16 * j) * PAD + k4 * 4]);
            #pragma unroll
            for (int c = 0; c < TCN; c++)
                cc[c] = *reinterpret_cast<const ulonglong2*>(
                            &scent[(ty + 16 * c) * PAD + k4 * 4]);
            #pragma unroll
            for (int j = 0; j < TV; j++)
                #pragma unroll
                for (int c = 0; c < TCN; c++) {
                    acc[j][c] = ffma2(vv[j].x, cc[c].x, acc[j][c]);
                    acc[j][c] = ffma2(vv[j].y, cc[c].y, acc[j][c]);
                }
        }

        #pragma unroll
        for (int c = 0; c < TCN; c++) {
            int   ci = t + ty + 16 * c;
            float cs = scsq[ty + 16 * c];
            #pragma unroll
            for (int j = 0; j < TV; j++) {
                float2 f  = unpack2(acc[j][c]);
                float  d2 = fmaf(-2.f, f.x + f.y, cs);
                if (d2 < bestd[j]) { bestd[j] = d2; besti[j] = ci; }
            }
        }
    }

    #pragma unroll
    for (int j = 0; j < TV; j++) {
        int v = tx + 16 * j;
        sredd[ty * BM + v] = bestd[j];
        sredi[ty * BM + v] = besti[j];
    }
    __syncthreads();
    if (tid < BM) {
        float bd = sredd[tid];
        int   bi2 = sredi[tid];
        #pragma unroll
        for (int r = 1; r < 16; r++) {
            float d  = sredd[r * BM + tid];
            int   i2 = sredi[r * BM + tid];
            if (d < bd || (d == bd && i2 < bi2)) { bd = d; bi2 = i2; }
        }
        // Overwrite the output row (duplicate padded rows write identical data).
        const float4* crow = reinterpret_cast<const float4*>(cents) + bi2 * 16;
        float4*       orow = reinterpret_cast<float4*>(out) + (size_t)srow[tid] * 16;
        #pragma unroll
        for (int j = 0; j < 16; j++) orow[j] = crow[j];
    }
}

// ---------------------------------------------------------------------------
extern "C" void kernel_launch(void* const* d_in, const int* in_sizes, int n_in,
                              void* d_out, int out_size) {
    const float* vecs  = (const float*)d_in[0];
    const float* cents = (const float*)d_in[1];
    float*       out   = (float*)d_out;

    const int n     = in_sizes[0] / DIM;   // 262144
    const int nlist = in_sizes[1] / DIM;   // 1024

    const int rescue_smem = (BM * PAD + BN * PAD + BN + 16 * BM) * 4
                          + 16 * BM * 4 + BM * 4;
    cudaFuncSetAttribute(assign_mma_kernel,
                         cudaFuncAttributeMaxDynamicSharedMemorySize, SMEM_B);
    cudaFuncSetAttribute(rescue_kernel,
                         cudaFuncAttributeMaxDynamicSharedMemorySize, rescue_smem);

    csq_kernel<<<(nlist + 255) / 256, 256>>>(cents, nlist);
    assign_mma_kernel<<<n / 128, 256, SMEM_B>>>(vecs, cents, out);
    rescue_kernel<<<n / BM, 256, rescue_smem>>>(vecs, cents, out, nlist);
}